// round 2
// baseline (speedup 1.0000x reference)
#include <cuda_runtime.h>
#include <math.h>

// Problem constants (fixed shapes from reference)
#define B_  4
#define H_  16
#define S_  2048
#define D_  1024
#define dh  64

#define BM  128   // q rows per CTA
#define BN  64    // key rows per tile
#define STRIDE 68 // smem row stride (floats), 16B-aligned, conflict-mitigating

#define NEGV (-1000000.0f)

// Scratch: Y = x_h @ W + b, layout [B*H, S, dh]  (32 MB)
__device__ float g_Y[(size_t)B_ * H_ * S_ * dh];

// ---------------------------------------------------------------------------
// Kernel 1: Y[bh, s, j] = sum_i x[b, s, h*64+i] * W[i, j] + bias[j]
// ---------------------------------------------------------------------------
__global__ void __launch_bounds__(256) y_kernel(const float* __restrict__ x,
                                                const float* __restrict__ W,
                                                const float* __restrict__ bias) {
    __shared__ float sW[dh][dh];   // 16 KB
    __shared__ float sX[4][dh];

    int tid = threadIdx.x;
    for (int i = tid; i < dh * dh; i += 256) sW[i / dh][i % dh] = W[i];

    int bh = blockIdx.x >> 4;                 // 16 blocks per (b,h)
    int s0 = (blockIdx.x & 15) * 128;
    int b  = bh >> 4;
    int h  = bh & 15;

    int j    = tid & 63;
    int rloc = tid >> 6;   // 0..3
    float bj = bias[j];
    __syncthreads();

    for (int chunk = 0; chunk < 128; chunk += 4) {
        {
            int r = tid >> 6, c = tid & 63;
            sX[r][c] = x[(size_t)(b * S_ + s0 + chunk + r) * D_ + h * 64 + c];
        }
        __syncthreads();
        float acc = bj;
        #pragma unroll
        for (int i = 0; i < 64; i++) acc += sX[rloc][i] * sW[i][j];
        g_Y[((size_t)bh * S_ + (s0 + chunk + rloc)) * 64 + j] = acc;
        __syncthreads();
    }
}

// ---------------------------------------------------------------------------
// Kernel 2: flash attention per (bh, q-tile of 128 rows).
//   scores = Yq . Yk^T / 64  (+ literal fp32 mask add) -> online softmax
//   -> acc += P . Xk
// 256 threads as (tx 0..15, ty 0..15); each thread owns 8 rows x 4 cols.
// The mask add MUST be done literally in fp32 (it quantizes the logits of
// masked rows to a 0.0625 grid — the reference depends on that rounding).
// ---------------------------------------------------------------------------
__global__ void __launch_bounds__(256) attn_kernel(const float* __restrict__ x,
                                                   const int*   __restrict__ mask,
                                                   float* __restrict__ out) {
    extern __shared__ float smem[];
    float* sYq = smem;                      // [BM][STRIDE]
    float* sYk = sYq + BM * STRIDE;         // [BN][STRIDE]
    float* sXk = sYk + BN * STRIDE;         // [BN][STRIDE]
    float* sP  = sXk + BN * STRIDE;         // [BM][STRIDE]

    int tid = threadIdx.x;
    int tx = tid & 15;
    int ty = tid >> 4;

    int bh = blockIdx.y;
    int b  = bh >> 4;
    int h  = bh & 15;
    int q0 = blockIdx.x * BM;

    const float* Ybh = g_Y + (size_t)bh * S_ * 64;

    // Load Yq tile (once per CTA)
    for (int i = tid; i < BM * 64; i += 256) {
        int r = i >> 6, c = i & 63;
        sYq[r * STRIDE + c] = Ybh[(size_t)(q0 + r) * 64 + c];
    }

    // Per-row additive mask value, exactly as reference: (1-mask)*(-1e6)
    float negv[8];
    #pragma unroll
    for (int rr = 0; rr < 8; rr++) {
        int m = mask[(size_t)b * S_ + q0 + ty * 8 + rr];
        negv[rr] = (1.0f - (float)m) * NEGV;
    }

    float m_i[8], l_i[8], acc[8][4];
    #pragma unroll
    for (int rr = 0; rr < 8; rr++) {
        m_i[rr] = -1e30f;
        l_i[rr] = 0.0f;
        #pragma unroll
        for (int cc = 0; cc < 4; cc++) acc[rr][cc] = 0.0f;
    }

    const float inv_d = 1.0f / 64.0f;

    for (int kt = 0; kt < S_ / BN; kt++) {
        __syncthreads();   // previous iteration's PV reads done
        // Load Yk and Xk tiles (64 x 64 each)
        for (int i = tid; i < BN * 64; i += 256) {
            int r = i >> 6, c = i & 63;
            sYk[r * STRIDE + c] = Ybh[(size_t)(kt * BN + r) * 64 + c];
            sXk[r * STRIDE + c] = x[(size_t)(b * S_ + kt * BN + r) * D_ + h * 64 + c];
        }
        __syncthreads();

        // ---- score GEMM: s[rr][cc] = Yq[row] . Yk[col] ----
        float s[8][4];
        #pragma unroll
        for (int rr = 0; rr < 8; rr++)
            #pragma unroll
            for (int cc = 0; cc < 4; cc++) s[rr][cc] = 0.0f;

        #pragma unroll
        for (int kk = 0; kk < 64; kk += 4) {
            float4 b0 = *(const float4*)&sYk[(4 * tx + 0) * STRIDE + kk];
            float4 b1 = *(const float4*)&sYk[(4 * tx + 1) * STRIDE + kk];
            float4 b2 = *(const float4*)&sYk[(4 * tx + 2) * STRIDE + kk];
            float4 b3 = *(const float4*)&sYk[(4 * tx + 3) * STRIDE + kk];
            #pragma unroll
            for (int rr = 0; rr < 8; rr++) {
                float4 a = *(const float4*)&sYq[(ty * 8 + rr) * STRIDE + kk];
                s[rr][0] += a.x * b0.x + a.y * b0.y + a.z * b0.z + a.w * b0.w;
                s[rr][1] += a.x * b1.x + a.y * b1.y + a.z * b1.z + a.w * b1.w;
                s[rr][2] += a.x * b2.x + a.y * b2.y + a.z * b2.z + a.w * b2.w;
                s[rr][3] += a.x * b3.x + a.y * b3.y + a.z * b3.z + a.w * b3.w;
            }
        }

        // ---- online softmax with literal fp32 mask add ----
        #pragma unroll
        for (int rr = 0; rr < 8; rr++) {
            #pragma unroll
            for (int cc = 0; cc < 4; cc++) {
                // Two separate roundings, same as the reference (no FMA!)
                s[rr][cc] = __fadd_rn(__fmul_rn(s[rr][cc], inv_d), negv[rr]);
            }

            float rmax = fmaxf(fmaxf(s[rr][0], s[rr][1]), fmaxf(s[rr][2], s[rr][3]));
            #pragma unroll
            for (int o = 8; o >= 1; o >>= 1)
                rmax = fmaxf(rmax, __shfl_xor_sync(0xffffffffu, rmax, o));

            float mn   = fmaxf(m_i[rr], rmax);
            float corr = __expf(m_i[rr] - mn);
            m_i[rr] = mn;

            float rs = 0.0f;
            #pragma unroll
            for (int cc = 0; cc < 4; cc++) {
                float p = __expf(s[rr][cc] - mn);
                s[rr][cc] = p;
                rs += p;
            }
            #pragma unroll
            for (int o = 8; o >= 1; o >>= 1)
                rs += __shfl_xor_sync(0xffffffffu, rs, o);

            l_i[rr] = l_i[rr] * corr + rs;
            #pragma unroll
            for (int cc = 0; cc < 4; cc++) acc[rr][cc] *= corr;

            *(float4*)&sP[(ty * 8 + rr) * STRIDE + 4 * tx] =
                make_float4(s[rr][0], s[rr][1], s[rr][2], s[rr][3]);
        }
        __syncthreads();   // P visible to all

        // ---- PV GEMM: acc[rr][cc] += P[row][j] * Xk[j][col] ----
        #pragma unroll
        for (int j = 0; j < 64; j += 4) {
            float4 x0 = *(const float4*)&sXk[(j + 0) * STRIDE + 4 * tx];
            float4 x1 = *(const float4*)&sXk[(j + 1) * STRIDE + 4 * tx];
            float4 x2 = *(const float4*)&sXk[(j + 2) * STRIDE + 4 * tx];
            float4 x3 = *(const float4*)&sXk[(j + 3) * STRIDE + 4 * tx];
            #pragma unroll
            for (int rr = 0; rr < 8; rr++) {
                float4 p = *(const float4*)&sP[(ty * 8 + rr) * STRIDE + j];
                acc[rr][0] += p.x * x0.x + p.y * x1.x + p.z * x2.x + p.w * x3.x;
                acc[rr][1] += p.x * x0.y + p.y * x1.y + p.z * x2.y + p.w * x3.y;
                acc[rr][2] += p.x * x0.z + p.y * x1.z + p.z * x2.z + p.w * x3.z;
                acc[rr][3] += p.x * x0.w + p.y * x1.w + p.z * x2.w + p.w * x3.w;
            }
        }
    }

    // ---- epilogue: out[bh, row, col] = acc / l  (flat [B,H,S,d] layout) ----
    float* outbh = out + (size_t)bh * S_ * 64;
    #pragma unroll
    for (int rr = 0; rr < 8; rr++) {
        float invl = 1.0f / l_i[rr];
        int row = q0 + ty * 8 + rr;
        float4 v = make_float4(acc[rr][0] * invl, acc[rr][1] * invl,
                               acc[rr][2] * invl, acc[rr][3] * invl);
        *(float4*)&outbh[(size_t)row * 64 + 4 * tx] = v;
    }
}

// ---------------------------------------------------------------------------
extern "C" void kernel_launch(void* const* d_in, const int* in_sizes, int n_in,
                              void* d_out, int out_size) {
    const float* x    = (const float*)d_in[0];
    const int*   mask = (const int*)d_in[1];
    const float* W    = (const float*)d_in[2];
    const float* bias = (const float*)d_in[3];
    float* out = (float*)d_out;

    // Kernel 1: Y = x_h @ W + b
    y_kernel<<<B_ * H_ * 16, 256>>>(x, W, bias);

    // Kernel 2: flash attention
    int smem_bytes = (2 * BM * STRIDE + 2 * BN * STRIDE) * (int)sizeof(float); // 104448
    cudaFuncSetAttribute(attn_kernel, cudaFuncAttributeMaxDynamicSharedMemorySize,
                         smem_bytes);
    dim3 grid(S_ / BM, B_ * H_);
    attn_kernel<<<grid, 256, smem_bytes>>>(x, mask, out);
}

// round 4
// speedup vs baseline: 4.2708x; 4.2708x over previous
#include <cuda_runtime.h>
#include <cuda_fp16.h>
#include <cstdint>
#include <math.h>

#define B_ 4
#define H_ 16
#define S_ 2048
#define D_ 1024
#define BH 64
#define dh 64
#define NEGV (-1000000.0f)

// ============================ device scratch ============================
__device__ __half g_Yhi[(size_t)BH * S_ * dh];
__device__ __half g_Ylo[(size_t)BH * S_ * dh];
__device__ __half g_XhiT[(size_t)BH * dh * S_];   // [bh][c][s]
__device__ __half g_XloT[(size_t)BH * dh * S_];

// ============================ PTX helpers ============================
__device__ __forceinline__ uint32_t smem_u32(const void* p) {
    uint32_t a;
    asm("{ .reg .u64 t; cvta.to.shared.u64 t, %1; cvt.u32.u64 %0, t; }" : "=r"(a) : "l"(p));
    return a;
}
#define LDSM_X4(r0, r1, r2, r3, addr) \
    asm volatile("ldmatrix.sync.aligned.m8n8.x4.shared.b16 {%0,%1,%2,%3}, [%4];" \
        : "=r"(r0), "=r"(r1), "=r"(r2), "=r"(r3) : "r"(addr))
#define CP_ASYNC16(dst, src) \
    asm volatile("cp.async.cg.shared.global [%0], [%1], 16;" :: "r"(dst), "l"(src))
#define CP_COMMIT() asm volatile("cp.async.commit_group;")
#define CP_WAIT0()  asm volatile("cp.async.wait_group 0;")

__device__ __forceinline__ void mma16816(float d[4], const uint32_t a[4], const uint32_t b[2]) {
    asm volatile(
        "mma.sync.aligned.m16n8k16.row.col.f32.f16.f16.f32 "
        "{%0,%1,%2,%3}, {%4,%5,%6,%7}, {%8,%9}, {%0,%1,%2,%3};"
        : "+f"(d[0]), "+f"(d[1]), "+f"(d[2]), "+f"(d[3])
        : "r"(a[0]), "r"(a[1]), "r"(a[2]), "r"(a[3]), "r"(b[0]), "r"(b[1]));
}
__device__ __forceinline__ uint32_t packh(float a, float b) {
    __half2 h = __floats2half2_rn(a, b);   // x=a (low), y=b (high)
    return *(uint32_t*)&h;
}

// ============================ prep kernels ============================
__global__ void __launch_bounds__(256) y_prep(const float* __restrict__ x,
                                              const float* __restrict__ W,
                                              const float* __restrict__ bias) {
    __shared__ float sW[dh][dh];
    __shared__ float sX[4][dh];
    int tid = threadIdx.x;
    for (int i = tid; i < dh * dh; i += 256) sW[i / dh][i % dh] = W[i];
    int bh = blockIdx.x >> 4;
    int s0 = (blockIdx.x & 15) * 128;
    int b = bh >> 4, h = bh & 15;
    int j = tid & 63, rloc = tid >> 6;
    float bj = bias[j];
    __syncthreads();
    for (int chunk = 0; chunk < 128; chunk += 4) {
        {
            int r = tid >> 6, c = tid & 63;
            sX[r][c] = x[(size_t)(b * S_ + s0 + chunk + r) * D_ + h * 64 + c];
        }
        __syncthreads();
        float acc = bj;
        #pragma unroll
        for (int i = 0; i < 64; i++) acc += sX[rloc][i] * sW[i][j];
        size_t idx = ((size_t)bh * S_ + (s0 + chunk + rloc)) * 64 + j;
        __half hi = __float2half_rn(acc);
        g_Yhi[idx] = hi;
        g_Ylo[idx] = __float2half_rn(acc - __half2float(hi));
        __syncthreads();
    }
}

__global__ void __launch_bounds__(256) x_prep(const float* __restrict__ x) {
    __shared__ float st[64 * 129];
    int tid = threadIdx.x;
    int bh = blockIdx.x >> 4;
    int s0 = (blockIdx.x & 15) * 128;
    int b = bh >> 4, h = bh & 15;
    for (int t = 0; t < 32; t++) {
        int i = tid + t * 256;
        int s = i >> 6, c = i & 63;
        st[c * 129 + s] = x[(size_t)(b * S_ + s0 + s) * D_ + h * 64 + c];
    }
    __syncthreads();
    for (int t = 0; t < 32; t++) {
        int i = tid + t * 256;
        int c = i >> 7, s = i & 127;
        float v = st[c * 129 + s];
        size_t idx = ((size_t)bh * 64 + c) * S_ + s0 + s;
        __half hi = __float2half_rn(v);
        g_XhiT[idx] = hi;
        g_XloT[idx] = __float2half_rn(v - __half2float(hi));
    }
}

// ============================ attention kernel ============================
// smem: 2 stages of 36864 B. Stage layout: YKH(9216) YKL(9216) XTH(9216) XTL(9216)
// Tiles: 64 rows x 64 halves, padded row stride = 144 B (conflict-free ldmatrix).
// Stage 0 initially holds Yq: YQH at 0 (128 x 144 = 18432), YQL at 18432.
#define STG 36864
#define ROWB 144

__device__ __forceinline__ void load_stage(uint32_t base, int bh, int kt, int tid) {
    #pragma unroll
    for (int t = 0; t < 8; t++) {
        int tile = t >> 1;                      // compile-time
        int idx  = ((t & 1) << 8) + tid;        // 0..511
        int n = idx >> 3, o = idx & 7;
        uint32_t dst = base + (uint32_t)tile * 9216u + (uint32_t)n * ROWB + (uint32_t)o * 16u;
        const __half* src;
        if (tile == 0)      src = g_Yhi  + ((size_t)bh * S_ + kt * 64 + n) * 64 + o * 8;
        else if (tile == 1) src = g_Ylo  + ((size_t)bh * S_ + kt * 64 + n) * 64 + o * 8;
        else if (tile == 2) src = g_XhiT + ((size_t)bh * 64 + n) * S_ + kt * 64 + o * 8;
        else                src = g_XloT + ((size_t)bh * 64 + n) * S_ + kt * 64 + o * 8;
        CP_ASYNC16(dst, src);
    }
    CP_COMMIT();
}

__global__ void __launch_bounds__(256, 1) attn_mma(const int* __restrict__ mask,
                                                   float* __restrict__ out) {
    extern __shared__ char smem[];
    uint32_t sb = smem_u32(smem);
    int tid = threadIdx.x;
    int w = tid >> 5, l = tid & 31;
    int bh = blockIdx.y, b = bh >> 4;
    int q0 = blockIdx.x * 128;

    // ---- Yq (hi/lo) -> stage0 via cp.async ----
    #pragma unroll
    for (int t = 0; t < 8; t++) {
        int sel = t >> 2;                        // 0: hi, 1: lo
        int ii  = ((t & 3) << 8) + tid;          // 0..1023
        int row = ii >> 3, o = ii & 7;
        uint32_t dst = sb + (uint32_t)sel * 18432u + (uint32_t)row * ROWB + (uint32_t)o * 16u;
        const __half* src = (sel ? g_Ylo : g_Yhi) + ((size_t)bh * S_ + q0 + row) * 64 + o * 8;
        CP_ASYNC16(dst, src);
    }
    CP_COMMIT();
    CP_WAIT0();
    __syncthreads();

    // ---- extract Yq A-fragments (persist in registers) ----
    uint32_t ahi[4][4], alo[4][4];
    #pragma unroll
    for (int j = 0; j < 4; j++) {
        uint32_t ad = sb + (uint32_t)(w * 16 + (l & 15)) * ROWB +
                      (uint32_t)(((l >> 4) * 8 + 16 * j) * 2);
        LDSM_X4(ahi[j][0], ahi[j][1], ahi[j][2], ahi[j][3], ad);
        LDSM_X4(alo[j][0], alo[j][1], alo[j][2], alo[j][3], ad + 18432u);
    }

    // ---- prefetch ktile 0 into stage1 (safe: targets stage1, frags read stage0) ----
    load_stage(sb + STG, bh, 0, tid);
    CP_WAIT0();
    __syncthreads();

    int R0 = q0 + w * 16 + (l >> 2);
    float negv0 = (1.0f - (float)mask[(size_t)b * S_ + R0]) * NEGV;
    float negv1 = (1.0f - (float)mask[(size_t)b * S_ + R0 + 8]) * NEGV;

    float pv[8][4];
    #pragma unroll
    for (int t = 0; t < 8; t++)
        #pragma unroll
        for (int q = 0; q < 4; q++) pv[t][q] = 0.0f;
    float l0 = 0.0f, l1 = 0.0f;

    uint32_t pAhi[4][4], pAlo[4][4];

    for (int kt = 0; kt < 32; kt++) {
        uint32_t cur = sb + (uint32_t)((kt + 1) & 1) * STG;
        if (kt < 31) load_stage(sb + (uint32_t)(kt & 1) * STG, bh, kt + 1, tid);

        // ---- scores + softmax + P-pack ----
        #pragma unroll
        for (int t = 0; t < 8; t++) {
            uint32_t b0 = cur + (uint32_t)(t * 8 + (l & 7)) * ROWB + (uint32_t)(((l >> 3) * 8) * 2);
            uint32_t bh0, bh1, bh2, bh3, bh4, bh5, bh6, bh7;
            uint32_t bl0, bl1, bl2, bl3, bl4, bl5, bl6, bl7;
            LDSM_X4(bh0, bh1, bh2, bh3, b0);
            LDSM_X4(bh4, bh5, bh6, bh7, b0 + 64u);
            LDSM_X4(bl0, bl1, bl2, bl3, b0 + 9216u);
            LDSM_X4(bl4, bl5, bl6, bl7, b0 + 9216u + 64u);
            uint32_t bhv[8] = {bh0, bh1, bh2, bh3, bh4, bh5, bh6, bh7};
            uint32_t blv[8] = {bl0, bl1, bl2, bl3, bl4, bl5, bl6, bl7};

            float s[4] = {0.0f, 0.0f, 0.0f, 0.0f};
            #pragma unroll
            for (int j = 0; j < 4; j++) {
                mma16816(s, ahi[j], &bhv[2 * j]);
                mma16816(s, alo[j], &bhv[2 * j]);
                mma16816(s, ahi[j], &blv[2 * j]);
            }

            // literal reference rounding: fl(score/64 + negv); shift back (exact)
            float lg0 = __fadd_rn(__fmul_rn(s[0], 0.015625f), negv0);
            float lg1 = __fadd_rn(__fmul_rn(s[1], 0.015625f), negv0);
            float lg2 = __fadd_rn(__fmul_rn(s[2], 0.015625f), negv1);
            float lg3 = __fadd_rn(__fmul_rn(s[3], 0.015625f), negv1);
            float p0 = __expf(lg0 - negv0);
            float p1 = __expf(lg1 - negv0);
            float p2 = __expf(lg2 - negv1);
            float p3 = __expf(lg3 - negv1);
            l0 += p0 + p1;
            l1 += p2 + p3;

            __half h0 = __float2half_rn(p0), h1 = __float2half_rn(p1);
            __half h2 = __float2half_rn(p2), h3 = __float2half_rn(p3);
            pAhi[t >> 1][(t & 1) * 2 + 0] = packh(p0, p1);
            pAhi[t >> 1][(t & 1) * 2 + 1] = packh(p2, p3);
            pAlo[t >> 1][(t & 1) * 2 + 0] = packh(p0 - __half2float(h0), p1 - __half2float(h1));
            pAlo[t >> 1][(t & 1) * 2 + 1] = packh(p2 - __half2float(h2), p3 - __half2float(h3));
        }

        // ---- PV: pv += P . X ----
        #pragma unroll
        for (int t2 = 0; t2 < 8; t2++) {
            uint32_t b0 = cur + 18432u + (uint32_t)(t2 * 8 + (l & 7)) * ROWB +
                          (uint32_t)(((l >> 3) * 8) * 2);
            uint32_t bh0, bh1, bh2, bh3, bh4, bh5, bh6, bh7;
            uint32_t bl0, bl1, bl2, bl3, bl4, bl5, bl6, bl7;
            LDSM_X4(bh0, bh1, bh2, bh3, b0);
            LDSM_X4(bh4, bh5, bh6, bh7, b0 + 64u);
            LDSM_X4(bl0, bl1, bl2, bl3, b0 + 9216u);
            LDSM_X4(bl4, bl5, bl6, bl7, b0 + 9216u + 64u);
            uint32_t bhv[8] = {bh0, bh1, bh2, bh3, bh4, bh5, bh6, bh7};
            uint32_t blv[8] = {bl0, bl1, bl2, bl3, bl4, bl5, bl6, bl7};
            #pragma unroll
            for (int j = 0; j < 4; j++) {
                mma16816(pv[t2], pAhi[j], &bhv[2 * j]);
                mma16816(pv[t2], pAlo[j], &bhv[2 * j]);
                mma16816(pv[t2], pAhi[j], &blv[2 * j]);
            }
        }

        CP_WAIT0();
        __syncthreads();
    }

    // ---- epilogue ----
    l0 += __shfl_xor_sync(0xffffffffu, l0, 1);
    l0 += __shfl_xor_sync(0xffffffffu, l0, 2);
    l1 += __shfl_xor_sync(0xffffffffu, l1, 1);
    l1 += __shfl_xor_sync(0xffffffffu, l1, 2);
    float i0 = 1.0f / l0, i1 = 1.0f / l1;

    #pragma unroll
    for (int t2 = 0; t2 < 8; t2++) {
        int c = t2 * 8 + (l & 3) * 2;
        float2 v0 = make_float2(pv[t2][0] * i0, pv[t2][1] * i0);
        float2 v1 = make_float2(pv[t2][2] * i1, pv[t2][3] * i1);
        *(float2*)(out + ((size_t)bh * S_ + R0) * 64 + c)     = v0;
        *(float2*)(out + ((size_t)bh * S_ + R0 + 8) * 64 + c) = v1;
    }
}

// ============================ launch ============================
extern "C" void kernel_launch(void* const* d_in, const int* in_sizes, int n_in,
                              void* d_out, int out_size) {
    const float* x    = (const float*)d_in[0];
    const int*   mask = (const int*)d_in[1];
    const float* W    = (const float*)d_in[2];
    const float* bias = (const float*)d_in[3];
    float* out = (float*)d_out;

    y_prep<<<BH * 16, 256>>>(x, W, bias);
    x_prep<<<BH * 16, 256>>>(x);

    cudaFuncSetAttribute(attn_mma, cudaFuncAttributeMaxDynamicSharedMemorySize, 2 * STG);
    dim3 grid(S_ / 128, BH);
    attn_mma<<<grid, 256, 2 * STG>>>(mask, out);
}

// round 5
// speedup vs baseline: 4.7185x; 1.1048x over previous
#include <cuda_runtime.h>
#include <cuda_fp16.h>
#include <cstdint>
#include <math.h>

#define B_ 4
#define H_ 16
#define S_ 2048
#define D_ 1024
#define BH 64
#define dh 64
#define NEGV (-1000000.0f)

// ============================ device scratch ============================
__device__ __half g_Yhi[(size_t)BH * S_ * dh];
__device__ __half g_Ylo[(size_t)BH * S_ * dh];
__device__ __half g_XhiT[(size_t)BH * dh * S_];   // [bh][c][s]
__device__ __half g_XloT[(size_t)BH * dh * S_];

// ============================ PTX helpers ============================
__device__ __forceinline__ uint32_t smem_u32(const void* p) {
    uint32_t a;
    asm("{ .reg .u64 t; cvta.to.shared.u64 t, %1; cvt.u32.u64 %0, t; }" : "=r"(a) : "l"(p));
    return a;
}
#define LDSM_X4(r0, r1, r2, r3, addr) \
    asm volatile("ldmatrix.sync.aligned.m8n8.x4.shared.b16 {%0,%1,%2,%3}, [%4];" \
        : "=r"(r0), "=r"(r1), "=r"(r2), "=r"(r3) : "r"(addr))
#define CP_ASYNC16(dst, src) \
    asm volatile("cp.async.cg.shared.global [%0], [%1], 16;" :: "r"(dst), "l"(src))
#define CP_COMMIT() asm volatile("cp.async.commit_group;")
#define CP_WAIT0()  asm volatile("cp.async.wait_group 0;")

__device__ __forceinline__ void mma16816(float d[4], const uint32_t a[4], const uint32_t b[2]) {
    asm volatile(
        "mma.sync.aligned.m16n8k16.row.col.f32.f16.f16.f32 "
        "{%0,%1,%2,%3}, {%4,%5,%6,%7}, {%8,%9}, {%0,%1,%2,%3};"
        : "+f"(d[0]), "+f"(d[1]), "+f"(d[2]), "+f"(d[3])
        : "r"(a[0]), "r"(a[1]), "r"(a[2]), "r"(a[3]), "r"(b[0]), "r"(b[1]));
}
__device__ __forceinline__ uint32_t packh(float a, float b) {
    __half2 h = __floats2half2_rn(a, b);
    return *(uint32_t*)&h;
}

// ============================ fused prep (MMA-based) ============================
// Per block: one (bh, 128-row chunk of s).
// 1) x tile fp32 -> fp16 hi/lo in smem
// 2) X^T hi/lo global writes (transpose gather from smem)
// 3) Y = x.W + b via 3-term split-fp16 MMA; split -> Yhi/Ylo global
// smem: sXh(18432) sXl(18432) sWh(9216) sWl(9216) = 55296 B
#define PROWB 144
#define PSXL 18432
#define PSWH 36864
#define PSWL 46080
#define PREP_SMEM 55296

__global__ void __launch_bounds__(256, 1) prep_mma(const float* __restrict__ x,
                                                   const float* __restrict__ W,
                                                   const float* __restrict__ bias) {
    extern __shared__ char smem[];
    uint32_t sb = smem_u32(smem);
    int tid = threadIdx.x;
    int w = tid >> 5, l = tid & 31;
    int bh = blockIdx.x >> 4;
    int s0 = (blockIdx.x & 15) * 128;
    int b = bh >> 4, h = bh & 15;

    // ---- W: load coalesced, transpose+split into sWh/sWl (Wt[n=j][k=i]) ----
    #pragma unroll
    for (int t = 0; t < 16; t++) {
        int idx = t * 256 + tid;
        int i = idx >> 6, j = idx & 63;
        float v = W[idx];
        __half hi = __float2half_rn(v);
        *(__half*)(smem + PSWH + j * PROWB + i * 2) = hi;
        *(__half*)(smem + PSWL + j * PROWB + i * 2) = __float2half_rn(v - __half2float(hi));
    }

    // ---- x tile: load float4, split, store hi/lo rows ----
    #pragma unroll
    for (int t = 0; t < 8; t++) {
        int idx = t * 256 + tid;
        int row = idx >> 4, q = idx & 15;
        float4 v = *(const float4*)(x + (size_t)(b * S_ + s0 + row) * D_ + h * 64 + q * 4);
        __half h0 = __float2half_rn(v.x), h1 = __float2half_rn(v.y);
        __half h2 = __float2half_rn(v.z), h3 = __float2half_rn(v.w);
        uint2 hiw = make_uint2(packh(v.x, v.y), packh(v.z, v.w));
        uint2 low = make_uint2(packh(v.x - __half2float(h0), v.y - __half2float(h1)),
                               packh(v.z - __half2float(h2), v.w - __half2float(h3)));
        *(uint2*)(smem + row * PROWB + q * 8) = hiw;
        *(uint2*)(smem + PSXL + row * PROWB + q * 8) = low;
    }
    __syncthreads();

    // ---- X^T global writes: gather 8 halves along s for fixed c ----
    #pragma unroll
    for (int t = 0; t < 8; t++) {
        int u = t * 256 + tid;
        int sel = u >> 10;           // 0 hi, 1 lo
        int c = (u >> 4) & 63;
        int g8 = u & 15;
        uint32_t base = (uint32_t)(sel ? PSXL : 0) + (uint32_t)c * 2;
        uint32_t pk[4];
        #pragma unroll
        for (int p = 0; p < 4; p++) {
            uint16_t a0 = *(const uint16_t*)(smem + base + (g8 * 8 + 2 * p) * PROWB);
            uint16_t a1 = *(const uint16_t*)(smem + base + (g8 * 8 + 2 * p + 1) * PROWB);
            pk[p] = (uint32_t)a0 | ((uint32_t)a1 << 16);
        }
        __half* dst = (sel ? g_XloT : g_XhiT) + ((size_t)bh * 64 + c) * S_ + s0 + g8 * 8;
        *(uint4*)dst = *(uint4*)pk;
    }

    // ---- Y via MMA: warp w owns rows w*16..w*16+15, all 64 cols ----
    uint32_t ahi[4][4], alo[4][4];
    #pragma unroll
    for (int j = 0; j < 4; j++) {
        uint32_t ad = sb + (uint32_t)(w * 16 + (l & 15)) * PROWB +
                      (uint32_t)(((l >> 4) * 8 + 16 * j) * 2);
        LDSM_X4(ahi[j][0], ahi[j][1], ahi[j][2], ahi[j][3], ad);
        LDSM_X4(alo[j][0], alo[j][1], alo[j][2], alo[j][3], ad + PSXL);
    }

    int R0 = w * 16 + (l >> 2);
    #pragma unroll
    for (int t2 = 0; t2 < 8; t2++) {
        uint32_t b0 = sb + PSWH + (uint32_t)(t2 * 8 + (l & 7)) * PROWB +
                      (uint32_t)(((l >> 3) * 8) * 2);
        uint32_t bh0, bh1, bh2, bh3, bh4, bh5, bh6, bh7;
        uint32_t bl0, bl1, bl2, bl3, bl4, bl5, bl6, bl7;
        LDSM_X4(bh0, bh1, bh2, bh3, b0);
        LDSM_X4(bh4, bh5, bh6, bh7, b0 + 64u);
        LDSM_X4(bl0, bl1, bl2, bl3, b0 + (PSWL - PSWH));
        LDSM_X4(bl4, bl5, bl6, bl7, b0 + (PSWL - PSWH) + 64u);
        uint32_t bhv[8] = {bh0, bh1, bh2, bh3, bh4, bh5, bh6, bh7};
        uint32_t blv[8] = {bl0, bl1, bl2, bl3, bl4, bl5, bl6, bl7};

        float y[4] = {0.0f, 0.0f, 0.0f, 0.0f};
        #pragma unroll
        for (int j = 0; j < 4; j++) {
            mma16816(y, ahi[j], &bhv[2 * j]);
            mma16816(y, alo[j], &bhv[2 * j]);
            mma16816(y, ahi[j], &blv[2 * j]);
        }

        int c = t2 * 8 + (l & 3) * 2;
        float b0f = bias[c], b1f = bias[c + 1];
        y[0] += b0f; y[1] += b1f; y[2] += b0f; y[3] += b1f;

        __half h0 = __float2half_rn(y[0]), h1 = __float2half_rn(y[1]);
        __half h2 = __float2half_rn(y[2]), h3 = __float2half_rn(y[3]);
        size_t o0 = ((size_t)bh * S_ + s0 + R0) * 64 + c;
        size_t o1 = ((size_t)bh * S_ + s0 + R0 + 8) * 64 + c;
        *(uint32_t*)(g_Yhi + o0) = packh(y[0], y[1]);
        *(uint32_t*)(g_Yhi + o1) = packh(y[2], y[3]);
        *(uint32_t*)(g_Ylo + o0) = packh(y[0] - __half2float(h0), y[1] - __half2float(h1));
        *(uint32_t*)(g_Ylo + o1) = packh(y[2] - __half2float(h2), y[3] - __half2float(h3));
    }
}

// ============================ attention kernel (unchanged core) ============================
#define STG 36864
#define ROWB 144

__device__ __forceinline__ void load_stage(uint32_t base, int bh, int kt, int tid) {
    #pragma unroll
    for (int t = 0; t < 8; t++) {
        int tile = t >> 1;
        int idx  = ((t & 1) << 8) + tid;
        int n = idx >> 3, o = idx & 7;
        uint32_t dst = base + (uint32_t)tile * 9216u + (uint32_t)n * ROWB + (uint32_t)o * 16u;
        const __half* src;
        if (tile == 0)      src = g_Yhi  + ((size_t)bh * S_ + kt * 64 + n) * 64 + o * 8;
        else if (tile == 1) src = g_Ylo  + ((size_t)bh * S_ + kt * 64 + n) * 64 + o * 8;
        else if (tile == 2) src = g_XhiT + ((size_t)bh * 64 + n) * S_ + kt * 64 + o * 8;
        else                src = g_XloT + ((size_t)bh * 64 + n) * S_ + kt * 64 + o * 8;
        CP_ASYNC16(dst, src);
    }
    CP_COMMIT();
}

__global__ void __launch_bounds__(256, 1) attn_mma(const int* __restrict__ mask,
                                                   float* __restrict__ out) {
    extern __shared__ char smem[];
    uint32_t sb = smem_u32(smem);
    int tid = threadIdx.x;
    int w = tid >> 5, l = tid & 31;
    int bh = blockIdx.y, b = bh >> 4;
    int q0 = blockIdx.x * 128;

    #pragma unroll
    for (int t = 0; t < 8; t++) {
        int sel = t >> 2;
        int ii  = ((t & 3) << 8) + tid;
        int row = ii >> 3, o = ii & 7;
        uint32_t dst = sb + (uint32_t)sel * 18432u + (uint32_t)row * ROWB + (uint32_t)o * 16u;
        const __half* src = (sel ? g_Ylo : g_Yhi) + ((size_t)bh * S_ + q0 + row) * 64 + o * 8;
        CP_ASYNC16(dst, src);
    }
    CP_COMMIT();
    CP_WAIT0();
    __syncthreads();

    uint32_t ahi[4][4], alo[4][4];
    #pragma unroll
    for (int j = 0; j < 4; j++) {
        uint32_t ad = sb + (uint32_t)(w * 16 + (l & 15)) * ROWB +
                      (uint32_t)(((l >> 4) * 8 + 16 * j) * 2);
        LDSM_X4(ahi[j][0], ahi[j][1], ahi[j][2], ahi[j][3], ad);
        LDSM_X4(alo[j][0], alo[j][1], alo[j][2], alo[j][3], ad + 18432u);
    }

    load_stage(sb + STG, bh, 0, tid);
    CP_WAIT0();
    __syncthreads();

    int R0 = q0 + w * 16 + (l >> 2);
    float negv0 = (1.0f - (float)mask[(size_t)b * S_ + R0]) * NEGV;
    float negv1 = (1.0f - (float)mask[(size_t)b * S_ + R0 + 8]) * NEGV;

    float pv[8][4];
    #pragma unroll
    for (int t = 0; t < 8; t++)
        #pragma unroll
        for (int q = 0; q < 4; q++) pv[t][q] = 0.0f;
    float l0 = 0.0f, l1 = 0.0f;

    uint32_t pAhi[4][4], pAlo[4][4];

    for (int kt = 0; kt < 32; kt++) {
        uint32_t cur = sb + (uint32_t)((kt + 1) & 1) * STG;
        if (kt < 31) load_stage(sb + (uint32_t)(kt & 1) * STG, bh, kt + 1, tid);

        #pragma unroll
        for (int t = 0; t < 8; t++) {
            uint32_t b0 = cur + (uint32_t)(t * 8 + (l & 7)) * ROWB + (uint32_t)(((l >> 3) * 8) * 2);
            uint32_t bh0, bh1, bh2, bh3, bh4, bh5, bh6, bh7;
            uint32_t bl0, bl1, bl2, bl3, bl4, bl5, bl6, bl7;
            LDSM_X4(bh0, bh1, bh2, bh3, b0);
            LDSM_X4(bh4, bh5, bh6, bh7, b0 + 64u);
            LDSM_X4(bl0, bl1, bl2, bl3, b0 + 9216u);
            LDSM_X4(bl4, bl5, bl6, bl7, b0 + 9216u + 64u);
            uint32_t bhv[8] = {bh0, bh1, bh2, bh3, bh4, bh5, bh6, bh7};
            uint32_t blv[8] = {bl0, bl1, bl2, bl3, bl4, bl5, bl6, bl7};

            float s[4] = {0.0f, 0.0f, 0.0f, 0.0f};
            #pragma unroll
            for (int j = 0; j < 4; j++) {
                mma16816(s, ahi[j], &bhv[2 * j]);
                mma16816(s, alo[j], &bhv[2 * j]);
                mma16816(s, ahi[j], &blv[2 * j]);
            }

            float lg0 = __fadd_rn(__fmul_rn(s[0], 0.015625f), negv0);
            float lg1 = __fadd_rn(__fmul_rn(s[1], 0.015625f), negv0);
            float lg2 = __fadd_rn(__fmul_rn(s[2], 0.015625f), negv1);
            float lg3 = __fadd_rn(__fmul_rn(s[3], 0.015625f), negv1);
            float p0 = __expf(lg0 - negv0);
            float p1 = __expf(lg1 - negv0);
            float p2 = __expf(lg2 - negv1);
            float p3 = __expf(lg3 - negv1);
            l0 += p0 + p1;
            l1 += p2 + p3;

            __half h0 = __float2half_rn(p0), h1 = __float2half_rn(p1);
            __half h2 = __float2half_rn(p2), h3 = __float2half_rn(p3);
            pAhi[t >> 1][(t & 1) * 2 + 0] = packh(p0, p1);
            pAhi[t >> 1][(t & 1) * 2 + 1] = packh(p2, p3);
            pAlo[t >> 1][(t & 1) * 2 + 0] = packh(p0 - __half2float(h0), p1 - __half2float(h1));
            pAlo[t >> 1][(t & 1) * 2 + 1] = packh(p2 - __half2float(h2), p3 - __half2float(h3));
        }

        #pragma unroll
        for (int t2 = 0; t2 < 8; t2++) {
            uint32_t b0 = cur + 18432u + (uint32_t)(t2 * 8 + (l & 7)) * ROWB +
                          (uint32_t)(((l >> 3) * 8) * 2);
            uint32_t bh0, bh1, bh2, bh3, bh4, bh5, bh6, bh7;
            uint32_t bl0, bl1, bl2, bl3, bl4, bl5, bl6, bl7;
            LDSM_X4(bh0, bh1, bh2, bh3, b0);
            LDSM_X4(bh4, bh5, bh6, bh7, b0 + 64u);
            LDSM_X4(bl0, bl1, bl2, bl3, b0 + 9216u);
            LDSM_X4(bl4, bl5, bl6, bl7, b0 + 9216u + 64u);
            uint32_t bhv[8] = {bh0, bh1, bh2, bh3, bh4, bh5, bh6, bh7};
            uint32_t blv[8] = {bl0, bl1, bl2, bl3, bl4, bl5, bl6, bl7};
            #pragma unroll
            for (int j = 0; j < 4; j++) {
                mma16816(pv[t2], pAhi[j], &bhv[2 * j]);
                mma16816(pv[t2], pAlo[j], &bhv[2 * j]);
                mma16816(pv[t2], pAhi[j], &blv[2 * j]);
            }
        }

        CP_WAIT0();
        __syncthreads();
    }

    l0 += __shfl_xor_sync(0xffffffffu, l0, 1);
    l0 += __shfl_xor_sync(0xffffffffu, l0, 2);
    l1 += __shfl_xor_sync(0xffffffffu, l1, 1);
    l1 += __shfl_xor_sync(0xffffffffu, l1, 2);
    float i0 = 1.0f / l0, i1 = 1.0f / l1;

    #pragma unroll
    for (int t2 = 0; t2 < 8; t2++) {
        int c = t2 * 8 + (l & 3) * 2;
        float2 v0 = make_float2(pv[t2][0] * i0, pv[t2][1] * i0);
        float2 v1 = make_float2(pv[t2][2] * i1, pv[t2][3] * i1);
        *(float2*)(out + ((size_t)bh * S_ + R0) * 64 + c)     = v0;
        *(float2*)(out + ((size_t)bh * S_ + R0 + 8) * 64 + c) = v1;
    }
}

// ============================ launch ============================
extern "C" void kernel_launch(void* const* d_in, const int* in_sizes, int n_in,
                              void* d_out, int out_size) {
    const float* x    = (const float*)d_in[0];
    const int*   mask = (const int*)d_in[1];
    const float* W    = (const float*)d_in[2];
    const float* bias = (const float*)d_in[3];
    float* out = (float*)d_out;

    cudaFuncSetAttribute(prep_mma, cudaFuncAttributeMaxDynamicSharedMemorySize, PREP_SMEM);
    prep_mma<<<BH * 16, 256, PREP_SMEM>>>(x, W, bias);

    cudaFuncSetAttribute(attn_mma, cudaFuncAttributeMaxDynamicSharedMemorySize, 2 * STG);
    dim3 grid(S_ / 128, BH);
    attn_mma<<<grid, 256, 2 * STG>>>(mask, out);
}

// round 6
// speedup vs baseline: 7.0685x; 1.4980x over previous
#include <cuda_runtime.h>
#include <cuda_fp16.h>
#include <cstdint>
#include <math.h>

#define B_ 4
#define H_ 16
#define S_ 2048
#define D_ 1024
#define BH 64
#define dh 64
#define NEGV (-1000000.0f)

// ============================ device scratch ============================
__device__ __half g_Yhi[(size_t)BH * S_ * dh];
__device__ __half g_Ylo[(size_t)BH * S_ * dh];
__device__ __half g_XhiT[(size_t)BH * dh * S_];   // [bh][c][s]

// ============================ PTX helpers ============================
__device__ __forceinline__ uint32_t smem_u32(const void* p) {
    uint32_t a;
    asm("{ .reg .u64 t; cvta.to.shared.u64 t, %1; cvt.u32.u64 %0, t; }" : "=r"(a) : "l"(p));
    return a;
}
#define LDSM_X4(r0, r1, r2, r3, addr) \
    asm volatile("ldmatrix.sync.aligned.m8n8.x4.shared.b16 {%0,%1,%2,%3}, [%4];" \
        : "=r"(r0), "=r"(r1), "=r"(r2), "=r"(r3) : "r"(addr))
#define CP_ASYNC16(dst, src) \
    asm volatile("cp.async.cg.shared.global [%0], [%1], 16;" :: "r"(dst), "l"(src))
#define CP_COMMIT() asm volatile("cp.async.commit_group;")
#define CP_WAIT0()  asm volatile("cp.async.wait_group 0;")

__device__ __forceinline__ void mma16816(float d[4], const uint32_t a[4], const uint32_t b[2]) {
    asm volatile(
        "mma.sync.aligned.m16n8k16.row.col.f32.f16.f16.f32 "
        "{%0,%1,%2,%3}, {%4,%5,%6,%7}, {%8,%9}, {%0,%1,%2,%3};"
        : "+f"(d[0]), "+f"(d[1]), "+f"(d[2]), "+f"(d[3])
        : "r"(a[0]), "r"(a[1]), "r"(a[2]), "r"(a[3]), "r"(b[0]), "r"(b[1]));
}
__device__ __forceinline__ uint32_t packh(float a, float b) {
    __half2 h = __floats2half2_rn(a, b);
    return *(uint32_t*)&h;
}

// ============================ fused prep (MMA-based) ============================
#define PROWB 144
#define PSXL 18432
#define PSWH 36864
#define PSWL 46080
#define PREP_SMEM 55296

__global__ void __launch_bounds__(256, 1) prep_mma(const float* __restrict__ x,
                                                   const float* __restrict__ W,
                                                   const float* __restrict__ bias) {
    extern __shared__ char smem[];
    uint32_t sb = smem_u32(smem);
    int tid = threadIdx.x;
    int w = tid >> 5, l = tid & 31;
    int bh = blockIdx.x >> 4;
    int s0 = (blockIdx.x & 15) * 128;
    int b = bh >> 4, h = bh & 15;

    // ---- W: load coalesced, transpose+split into sWh/sWl ----
    #pragma unroll
    for (int t = 0; t < 16; t++) {
        int idx = t * 256 + tid;
        int i = idx >> 6, j = idx & 63;
        float v = W[idx];
        __half hi = __float2half_rn(v);
        *(__half*)(smem + PSWH + j * PROWB + i * 2) = hi;
        *(__half*)(smem + PSWL + j * PROWB + i * 2) = __float2half_rn(v - __half2float(hi));
    }

    // ---- x tile: load float4, split, store hi/lo rows ----
    #pragma unroll
    for (int t = 0; t < 8; t++) {
        int idx = t * 256 + tid;
        int row = idx >> 4, q = idx & 15;
        float4 v = *(const float4*)(x + (size_t)(b * S_ + s0 + row) * D_ + h * 64 + q * 4);
        __half h0 = __float2half_rn(v.x), h1 = __float2half_rn(v.y);
        __half h2 = __float2half_rn(v.z), h3 = __float2half_rn(v.w);
        uint2 hiw = make_uint2(packh(v.x, v.y), packh(v.z, v.w));
        uint2 low = make_uint2(packh(v.x - __half2float(h0), v.y - __half2float(h1)),
                               packh(v.z - __half2float(h2), v.w - __half2float(h3)));
        *(uint2*)(smem + row * PROWB + q * 8) = hiw;
        *(uint2*)(smem + PSXL + row * PROWB + q * 8) = low;
    }
    __syncthreads();

    // ---- X^T (hi only) global writes: gather 8 halves along s for fixed c ----
    #pragma unroll
    for (int t = 0; t < 4; t++) {
        int u = t * 256 + tid;
        int c = (u >> 4) & 63;
        int g8 = u & 15;
        uint32_t base = (uint32_t)c * 2;
        uint32_t pk[4];
        #pragma unroll
        for (int p = 0; p < 4; p++) {
            uint16_t a0 = *(const uint16_t*)(smem + base + (g8 * 8 + 2 * p) * PROWB);
            uint16_t a1 = *(const uint16_t*)(smem + base + (g8 * 8 + 2 * p + 1) * PROWB);
            pk[p] = (uint32_t)a0 | ((uint32_t)a1 << 16);
        }
        __half* dst = g_XhiT + ((size_t)bh * 64 + c) * S_ + s0 + g8 * 8;
        *(uint4*)dst = *(uint4*)pk;
    }

    // ---- Y via MMA: warp w owns rows w*16..w*16+15, all 64 cols ----
    uint32_t ahi[4][4], alo[4][4];
    #pragma unroll
    for (int j = 0; j < 4; j++) {
        uint32_t ad = sb + (uint32_t)(w * 16 + (l & 15)) * PROWB +
                      (uint32_t)(((l >> 4) * 8 + 16 * j) * 2);
        LDSM_X4(ahi[j][0], ahi[j][1], ahi[j][2], ahi[j][3], ad);
        LDSM_X4(alo[j][0], alo[j][1], alo[j][2], alo[j][3], ad + PSXL);
    }

    int R0 = w * 16 + (l >> 2);
    #pragma unroll
    for (int t2 = 0; t2 < 8; t2++) {
        uint32_t b0 = sb + PSWH + (uint32_t)(t2 * 8 + (l & 7)) * PROWB +
                      (uint32_t)(((l >> 3) * 8) * 2);
        uint32_t bh0, bh1, bh2, bh3, bh4, bh5, bh6, bh7;
        uint32_t bl0, bl1, bl2, bl3, bl4, bl5, bl6, bl7;
        LDSM_X4(bh0, bh1, bh2, bh3, b0);
        LDSM_X4(bh4, bh5, bh6, bh7, b0 + 64u);
        LDSM_X4(bl0, bl1, bl2, bl3, b0 + (PSWL - PSWH));
        LDSM_X4(bl4, bl5, bl6, bl7, b0 + (PSWL - PSWH) + 64u);
        uint32_t bhv[8] = {bh0, bh1, bh2, bh3, bh4, bh5, bh6, bh7};
        uint32_t blv[8] = {bl0, bl1, bl2, bl3, bl4, bl5, bl6, bl7};

        float y[4] = {0.0f, 0.0f, 0.0f, 0.0f};
        #pragma unroll
        for (int j = 0; j < 4; j++) {
            mma16816(y, ahi[j], &bhv[2 * j]);
            mma16816(y, alo[j], &bhv[2 * j]);
            mma16816(y, ahi[j], &blv[2 * j]);
        }

        int c = t2 * 8 + (l & 3) * 2;
        float b0f = bias[c], b1f = bias[c + 1];
        y[0] += b0f; y[1] += b1f; y[2] += b0f; y[3] += b1f;

        __half h0 = __float2half_rn(y[0]), h1 = __float2half_rn(y[1]);
        __half h2 = __float2half_rn(y[2]), h3 = __float2half_rn(y[3]);
        size_t o0 = ((size_t)bh * S_ + s0 + R0) * 64 + c;
        size_t o1 = ((size_t)bh * S_ + s0 + R0 + 8) * 64 + c;
        *(uint32_t*)(g_Yhi + o0) = packh(y[0], y[1]);
        *(uint32_t*)(g_Yhi + o1) = packh(y[2], y[3]);
        *(uint32_t*)(g_Ylo + o0) = packh(y[0] - __half2float(h0), y[1] - __half2float(h1));
        *(uint32_t*)(g_Ylo + o1) = packh(y[2] - __half2float(h2), y[3] - __half2float(h3));
    }
}

// ============================ attention kernel ============================
// Stage layout (27648 B): YKH(0) YKL(9216) XTH(18432). Two stages.
// Yq (hi at sb+0, lo at sb+18432) occupies [0,36864) transiently; its frags
// are extracted to registers before any stage prefetch overwrites the region.
#define STG 27648
#define ROWB 144

__device__ __forceinline__ void load_stage(uint32_t base, int bh, int kt, int tid) {
    #pragma unroll
    for (int t = 0; t < 6; t++) {
        int tile = t >> 1;                      // 0: Yhi, 1: Ylo, 2: XhiT
        int idx  = ((t & 1) << 8) + tid;        // 0..511
        int n = idx >> 3, o = idx & 7;
        uint32_t dst = base + (uint32_t)tile * 9216u + (uint32_t)n * ROWB + (uint32_t)o * 16u;
        const __half* src;
        if (tile == 0)      src = g_Yhi  + ((size_t)bh * S_ + kt * 64 + n) * 64 + o * 8;
        else if (tile == 1) src = g_Ylo  + ((size_t)bh * S_ + kt * 64 + n) * 64 + o * 8;
        else                src = g_XhiT + ((size_t)bh * 64 + n) * S_ + kt * 64 + o * 8;
        CP_ASYNC16(dst, src);
    }
    CP_COMMIT();
}

__global__ void __launch_bounds__(256, 1) attn_mma(const int* __restrict__ mask,
                                                   float* __restrict__ out) {
    extern __shared__ char smem[];
    uint32_t sb = smem_u32(smem);
    int tid = threadIdx.x;
    int w = tid >> 5, l = tid & 31;
    int bh = blockIdx.y, b = bh >> 4;
    int q0 = blockIdx.x * 128;

    // ---- Yq (hi/lo) into [0, 36864) via cp.async ----
    #pragma unroll
    for (int t = 0; t < 8; t++) {
        int sel = t >> 2;
        int ii  = ((t & 3) << 8) + tid;
        int row = ii >> 3, o = ii & 7;
        uint32_t dst = sb + (uint32_t)sel * 18432u + (uint32_t)row * ROWB + (uint32_t)o * 16u;
        const __half* src = (sel ? g_Ylo : g_Yhi) + ((size_t)bh * S_ + q0 + row) * 64 + o * 8;
        CP_ASYNC16(dst, src);
    }
    CP_COMMIT();
    CP_WAIT0();
    __syncthreads();

    // ---- extract Yq A-fragments (before stage prefetch clobbers region) ----
    uint32_t ahi[4][4], alo[4][4];
    #pragma unroll
    for (int j = 0; j < 4; j++) {
        uint32_t ad = sb + (uint32_t)(w * 16 + (l & 15)) * ROWB +
                      (uint32_t)(((l >> 4) * 8 + 16 * j) * 2);
        LDSM_X4(ahi[j][0], ahi[j][1], ahi[j][2], ahi[j][3], ad);
        LDSM_X4(alo[j][0], alo[j][1], alo[j][2], alo[j][3], ad + 18432u);
    }
    __syncthreads();   // all warps done reading Yq before prefetch overwrites

    // ---- prefetch ktile 0 into stage1 ----
    load_stage(sb + STG, bh, 0, tid);
    CP_WAIT0();
    __syncthreads();

    int R0 = q0 + w * 16 + (l >> 2);
    float negv0 = (1.0f - (float)mask[(size_t)b * S_ + R0]) * NEGV;
    float negv1 = (1.0f - (float)mask[(size_t)b * S_ + R0 + 8]) * NEGV;

    float pv[8][4];
    #pragma unroll
    for (int t = 0; t < 8; t++)
        #pragma unroll
        for (int q = 0; q < 4; q++) pv[t][q] = 0.0f;
    float l0 = 0.0f, l1 = 0.0f;

    uint32_t pAhi[4][4];

    for (int kt = 0; kt < 32; kt++) {
        uint32_t cur = sb + (uint32_t)((kt + 1) & 1) * STG;
        if (kt < 31) load_stage(sb + (uint32_t)(kt & 1) * STG, bh, kt + 1, tid);

        // ---- scores (3-term) + softmax + P-pack (fp16 only) ----
        #pragma unroll
        for (int t = 0; t < 8; t++) {
            uint32_t b0 = cur + (uint32_t)(t * 8 + (l & 7)) * ROWB + (uint32_t)(((l >> 3) * 8) * 2);
            uint32_t bh0, bh1, bh2, bh3, bh4, bh5, bh6, bh7;
            uint32_t bl0, bl1, bl2, bl3, bl4, bl5, bl6, bl7;
            LDSM_X4(bh0, bh1, bh2, bh3, b0);
            LDSM_X4(bh4, bh5, bh6, bh7, b0 + 64u);
            LDSM_X4(bl0, bl1, bl2, bl3, b0 + 9216u);
            LDSM_X4(bl4, bl5, bl6, bl7, b0 + 9216u + 64u);
            uint32_t bhv[8] = {bh0, bh1, bh2, bh3, bh4, bh5, bh6, bh7};
            uint32_t blv[8] = {bl0, bl1, bl2, bl3, bl4, bl5, bl6, bl7};

            float s[4] = {0.0f, 0.0f, 0.0f, 0.0f};
            #pragma unroll
            for (int j = 0; j < 4; j++) {
                mma16816(s, ahi[j], &bhv[2 * j]);
                mma16816(s, alo[j], &bhv[2 * j]);
                mma16816(s, ahi[j], &blv[2 * j]);
            }

            float lg0 = __fadd_rn(__fmul_rn(s[0], 0.015625f), negv0);
            float lg1 = __fadd_rn(__fmul_rn(s[1], 0.015625f), negv0);
            float lg2 = __fadd_rn(__fmul_rn(s[2], 0.015625f), negv1);
            float lg3 = __fadd_rn(__fmul_rn(s[3], 0.015625f), negv1);
            float p0 = __expf(lg0 - negv0);
            float p1 = __expf(lg1 - negv0);
            float p2 = __expf(lg2 - negv1);
            float p3 = __expf(lg3 - negv1);
            l0 += p0 + p1;
            l1 += p2 + p3;

            pAhi[t >> 1][(t & 1) * 2 + 0] = packh(p0, p1);
            pAhi[t >> 1][(t & 1) * 2 + 1] = packh(p2, p3);
        }

        // ---- PV (1-term): pv += P_hi . X_hi ----
        #pragma unroll
        for (int t2 = 0; t2 < 8; t2++) {
            uint32_t b0 = cur + 18432u + (uint32_t)(t2 * 8 + (l & 7)) * ROWB +
                          (uint32_t)(((l >> 3) * 8) * 2);
            uint32_t bh0, bh1, bh2, bh3, bh4, bh5, bh6, bh7;
            LDSM_X4(bh0, bh1, bh2, bh3, b0);
            LDSM_X4(bh4, bh5, bh6, bh7, b0 + 64u);
            uint32_t bhv[8] = {bh0, bh1, bh2, bh3, bh4, bh5, bh6, bh7};
            #pragma unroll
            for (int j = 0; j < 4; j++)
                mma16816(pv[t2], pAhi[j], &bhv[2 * j]);
        }

        CP_WAIT0();
        __syncthreads();
    }

    // ---- epilogue ----
    l0 += __shfl_xor_sync(0xffffffffu, l0, 1);
    l0 += __shfl_xor_sync(0xffffffffu, l0, 2);
    l1 += __shfl_xor_sync(0xffffffffu, l1, 1);
    l1 += __shfl_xor_sync(0xffffffffu, l1, 2);
    float i0 = 1.0f / l0, i1 = 1.0f / l1;

    #pragma unroll
    for (int t2 = 0; t2 < 8; t2++) {
        int c = t2 * 8 + (l & 3) * 2;
        float2 v0 = make_float2(pv[t2][0] * i0, pv[t2][1] * i0);
        float2 v1 = make_float2(pv[t2][2] * i1, pv[t2][3] * i1);
        *(float2*)(out + ((size_t)bh * S_ + R0) * 64 + c)     = v0;
        *(float2*)(out + ((size_t)bh * S_ + R0 + 8) * 64 + c) = v1;
    }
}

// ============================ launch ============================
extern "C" void kernel_launch(void* const* d_in, const int* in_sizes, int n_in,
                              void* d_out, int out_size) {
    const float* x    = (const float*)d_in[0];
    const int*   mask = (const int*)d_in[1];
    const float* W    = (const float*)d_in[2];
    const float* bias = (const float*)d_in[3];
    float* out = (float*)d_out;

    cudaFuncSetAttribute(prep_mma, cudaFuncAttributeMaxDynamicSharedMemorySize, PREP_SMEM);
    prep_mma<<<BH * 16, 256, PREP_SMEM>>>(x, W, bias);

    cudaFuncSetAttribute(attn_mma, cudaFuncAttributeMaxDynamicSharedMemorySize, 2 * STG);
    dim3 grid(S_ / 128, BH);
    attn_mma<<<grid, 256, 2 * STG>>>(mask, out);
}